// round 14
// baseline (speedup 1.0000x reference)
#include <cuda_runtime.h>
#include <cuda_fp16.h>
#include <math.h>
#include <cstdint>

// ---------------- problem constants ----------------
#define Vv   30522
#define Hh   768
#define Ll   12
#define FFf  3072
#define NHh  12
#define DHh  64
#define Bb   32
#define Ss   128
#define NLl  10000
#define NTOK (Bb*Ss)          // 4096
#define QKVN (3*Hh)           // 2304
#define EPS_LN  1e-12f
#define EPS_COS 1e-8f

// transposed fp16 weight layout per layer (element offsets)
#define OFF_O   (QKVN*Hh)             // after packed qkv [2304][768]
#define OFF_W1  (OFF_O + Hh*Hh)       // [3072][768]
#define OFF_W2  (OFF_W1 + Hh*FFf)     // [768][3072]
#define LSTRIDE (OFF_W2 + FFf*Hh)     // 7,077,888

// ---------------- device scratch ----------------
__device__ __half g_wth[Ll*LSTRIDE];           // fp16 weights, transposed [N][K]
__device__ float  g_bqkv[Ll*QKVN];
__device__ float  g_zeros[Hh];                 // stays zero (module-load zero-init)

__device__ float  g_x  [NTOK*Hh];
__device__ __half g_xhi[NTOK*Hh];
__device__ float  g_qkv[NTOK*QKVN];
__device__ __half g_chi[NTOK*Hh];
__device__ __half g_hhi[NTOK*FFf];
__device__ float  g_y  [NTOK*Hh];
__device__ float  g_y2 [NTOK*Hh];
__device__ float  g_y3 [NTOK*Hh];
__device__ float  g_y4 [NTOK*Hh];
__device__ float g_mbias[NTOK];
__device__ float g_cls[Bb*Hh];
__device__ float g_cn [Bb];
__device__ unsigned long long g_best[Bb];

// ---------------- PTX helpers (compute_100-safe) ----------------
__device__ __forceinline__ uint32_t smem_u32(const void* p) {
    uint32_t a;
    asm("{ .reg .u64 t; cvta.to.shared.u64 t, %1; cvt.u32.u64 %0, t; }" : "=r"(a) : "l"(p));
    return a;
}
__device__ __forceinline__ void cp_async16(uint32_t dst, const void* src) {
    asm volatile("cp.async.cg.shared.global [%0], [%1], 16;" :: "r"(dst), "l"(src) : "memory");
}
#define CP_COMMIT() asm volatile("cp.async.commit_group;" ::: "memory")
#define CP_WAIT(n)  asm volatile("cp.async.wait_group %0;" :: "n"(n) : "memory")

__device__ __forceinline__ void ldsm4(uint32_t& r0, uint32_t& r1, uint32_t& r2, uint32_t& r3,
                                      uint32_t addr) {
    asm volatile("ldmatrix.sync.aligned.m8n8.x4.shared.b16 {%0,%1,%2,%3}, [%4];"
                 : "=r"(r0), "=r"(r1), "=r"(r2), "=r"(r3) : "r"(addr));
}
__device__ __forceinline__ void mma16816(float* c, uint32_t a0, uint32_t a1, uint32_t a2,
                                         uint32_t a3, uint32_t b0, uint32_t b1) {
    asm volatile(
        "mma.sync.aligned.m16n8k16.row.col.f32.f16.f16.f32 "
        "{%0,%1,%2,%3}, {%4,%5,%6,%7}, {%8,%9}, {%0,%1,%2,%3};"
        : "+f"(c[0]), "+f"(c[1]), "+f"(c[2]), "+f"(c[3])
        : "r"(a0), "r"(a1), "r"(a2), "r"(a3), "r"(b0), "r"(b1));
}

// ---------------- misc helpers ----------------
__device__ __forceinline__ float blk_sum256(float v, volatile float* sred) {
    int lane = threadIdx.x & 31, w = threadIdx.x >> 5;
    #pragma unroll
    for (int o = 16; o > 0; o >>= 1) v += __shfl_down_sync(0xffffffffu, v, o);
    if (lane == 0) sred[w] = v;
    __syncthreads();
    if (threadIdx.x == 0) {
        float s = 0.f;
        #pragma unroll
        for (int i = 0; i < 8; i++) s += sred[i];
        sred[8] = s;
    }
    __syncthreads();
    float r = sred[8];
    __syncthreads();
    return r;
}
__device__ __forceinline__ float gelu_tanh(float x) {
    float x3 = x * x * x;
    float t = tanhf(0.7978845608028654f * (x + 0.044715f * x3));
    return 0.5f * x * (1.0f + t);
}
__device__ __forceinline__ unsigned long long pack_key(float c, int l) {
    unsigned u = __float_as_uint(c);
    u = (u & 0x80000000u) ? ~u : (u | 0x80000000u);
    return ((unsigned long long)u << 32) | (unsigned long long)(0xFFFFFFFFu - (unsigned)l);
}
__device__ __forceinline__ unsigned pack2h(float v0, float v1) {
    __half h0 = __float2half(v0), h1 = __float2half(v1);
    return (unsigned)__half_as_ushort(h0) | ((unsigned)__half_as_ushort(h1) << 16);
}

// ---------------- weight transpose to fp16 ----------------
__global__ void wsplit4_kernel(const float* __restrict__ W0, const float* __restrict__ W1m,
                               const float* __restrict__ W2m, const float* __restrict__ W3m) {
    __shared__ float t[32][33];
    int z = blockIdx.z;
    int m = z & 3, l = z >> 2;
    const float* Ws = (m == 0 ? W0 : m == 1 ? W1m : m == 2 ? W2m : W3m) + (size_t)l * Hh * Hh;
    long dstOff = (m < 3) ? (long)m * Hh * Hh : (long)OFF_O;
    __half* th = g_wth + (size_t)l * LSTRIDE + dstOff;
    int n = blockIdx.x * 32 + threadIdx.x;
    #pragma unroll
    for (int i = 0; i < 4; i++) {
        int k = blockIdx.y * 32 + threadIdx.y + i * 8;
        t[threadIdx.y + i * 8][threadIdx.x] = Ws[(size_t)k * Hh + n];
    }
    __syncthreads();
    int k2 = blockIdx.y * 32 + threadIdx.x;
    #pragma unroll
    for (int i = 0; i < 4; i++) {
        int n2 = blockIdx.x * 32 + threadIdx.y + i * 8;
        th[(size_t)n2 * Hh + k2] = __float2half(t[threadIdx.x][threadIdx.y + i * 8]);
    }
}

__global__ void wsplit_kernel(const float* __restrict__ W, long dstOff, int K, int N) {
    __shared__ float t[32][33];
    int l = blockIdx.z;
    const float* Ws = W + (size_t)l * K * N;
    __half* th = g_wth + (size_t)l * LSTRIDE + dstOff;
    int n = blockIdx.x * 32 + threadIdx.x;
    #pragma unroll
    for (int i = 0; i < 4; i++) {
        int k = blockIdx.y * 32 + threadIdx.y + i * 8;
        t[threadIdx.y + i * 8][threadIdx.x] = Ws[(size_t)k * N + n];
    }
    __syncthreads();
    int k2 = blockIdx.y * 32 + threadIdx.x;
    #pragma unroll
    for (int i = 0; i < 4; i++) {
        int n2 = blockIdx.x * 32 + threadIdx.y + i * 8;
        th[(size_t)n2 * K + k2] = __float2half(t[threadIdx.x][threadIdx.y + i * 8]);
    }
}

__global__ void pack_bias_kernel(const float* __restrict__ bq, const float* __restrict__ bk,
                                 const float* __restrict__ bv) {
    int l = blockIdx.x, j = threadIdx.x;
    g_bqkv[l * QKVN + j]          = bq[l * Hh + j];
    g_bqkv[l * QKVN + Hh + j]     = bk[l * Hh + j];
    g_bqkv[l * QKVN + 2 * Hh + j] = bv[l * Hh + j];
}

// ---------------- embeddings + LN + mask bias ----------------
__global__ void embed_ln_kernel(const int* __restrict__ ids, const int* __restrict__ tys,
                                const float* __restrict__ word, const float* __restrict__ pos,
                                const float* __restrict__ typ,
                                const float* __restrict__ eg, const float* __restrict__ eb) {
    __shared__ float sred[9];
    int t = blockIdx.x;
    int s = t & (Ss - 1);
    int id = ids[t], ty = tys[t];
    float v[3];
    float loc = 0.f;
    #pragma unroll
    for (int i = 0; i < 3; i++) {
        int j = threadIdx.x + i * 256;
        v[i] = word[(size_t)id * Hh + j] + pos[(size_t)s * Hh + j] + typ[(size_t)ty * Hh + j];
        loc += v[i];
    }
    float mu = blk_sum256(loc, sred) * (1.0f / Hh);
    float l2 = 0.f;
    #pragma unroll
    for (int i = 0; i < 3; i++) { float d = v[i] - mu; l2 += d * d; }
    float var = blk_sum256(l2, sred) * (1.0f / Hh);
    float rstd = rsqrtf(var + EPS_LN);
    #pragma unroll
    for (int i = 0; i < 3; i++) {
        int j = threadIdx.x + i * 256;
        size_t idx = (size_t)t * Hh + j;
        float o = (v[i] - mu) * rstd * eg[j] + eb[j];
        g_x[idx] = o;
        g_xhi[idx] = __float2half(o);
    }
    if (threadIdx.x == 0) g_mbias[t] = (id > 0) ? 0.f : -10000.0f;
}

// ---------------- residual add (3-way) + LN ----------------
__global__ void add_ln3_kernel(float* __restrict__ x, const float* __restrict__ y,
                               const float* __restrict__ y2,
                               const float* __restrict__ g, const float* __restrict__ b) {
    __shared__ float sred[9];
    size_t base = (size_t)blockIdx.x * Hh;
    float v[3];
    float loc = 0.f;
    #pragma unroll
    for (int i = 0; i < 3; i++) {
        int j = threadIdx.x + i * 256;
        v[i] = x[base + j] + y[base + j] + y2[base + j];
        loc += v[i];
    }
    float mu = blk_sum256(loc, sred) * (1.0f / Hh);
    float l2 = 0.f;
    #pragma unroll
    for (int i = 0; i < 3; i++) { float d = v[i] - mu; l2 += d * d; }
    float var = blk_sum256(l2, sred) * (1.0f / Hh);
    float rstd = rsqrtf(var + EPS_LN);
    #pragma unroll
    for (int i = 0; i < 3; i++) {
        int j = threadIdx.x + i * 256;
        float o = (v[i] - mu) * rstd * g[j] + b[j];
        x[base + j] = o;
        g_xhi[base + j] = __float2half(o);
    }
}

// ---------------- residual add (5-way) + LN (for split-K4 W2) ----------------
__global__ void add_ln5_kernel(float* __restrict__ x, const float* __restrict__ y,
                               const float* __restrict__ y2, const float* __restrict__ y3,
                               const float* __restrict__ y4,
                               const float* __restrict__ g, const float* __restrict__ b) {
    __shared__ float sred[9];
    size_t base = (size_t)blockIdx.x * Hh;
    float v[3];
    float loc = 0.f;
    #pragma unroll
    for (int i = 0; i < 3; i++) {
        int j = threadIdx.x + i * 256;
        v[i] = x[base + j] + y[base + j] + y2[base + j] + y3[base + j] + y4[base + j];
        loc += v[i];
    }
    float mu = blk_sum256(loc, sred) * (1.0f / Hh);
    float l2 = 0.f;
    #pragma unroll
    for (int i = 0; i < 3; i++) { float d = v[i] - mu; l2 += d * d; }
    float var = blk_sum256(l2, sred) * (1.0f / Hh);
    float rstd = rsqrtf(var + EPS_LN);
    #pragma unroll
    for (int i = 0; i < 3; i++) {
        int j = threadIdx.x + i * 256;
        float o = (v[i] - mu) * rstd * g[j] + b[j];
        x[base + j] = o;
        g_xhi[base + j] = __float2half(o);
    }
}

// ---------------- HMMA fp16 GEMM: C[4096, N] = Ah @ Bh^T + bias ----------------
// K-split via gridDim.z (OUTMODE 0): z=0 -> Cf with bias, z>=1 -> Cfz zero-bias.
// OUTMODE 1: gelu -> fp16 out. CTA 128x128, K-chunk 64 (rows 144B), 3-stage
// cp.async pipeline (ONE __syncthreads per chunk), 8 warps, 2 CTAs/SM.
#define GT_ROW   144
#define GT_TILE  (128 * GT_ROW)        // 18432 B per sub-tile
#define GT_STAGE (2 * GT_TILE)         // Ah | Bh = 36864
#define NSTAGE   3
#define GSMEM    (NSTAGE * GT_STAGE)   // 110592
template <int OUTMODE>
__global__ void __launch_bounds__(256, 2) gemm_mma(
    const __half* __restrict__ Ahi,
    const __half* __restrict__ Bh,
    const float* __restrict__ bias,
    float* __restrict__ Cf, float* __restrict__ Cf2,
    float* __restrict__ Cf3, float* __restrict__ Cf4,
    __half* __restrict__ Chi,
    int Kfull, int Klen, int ldc)
{
    extern __shared__ char sm[];
    const uint32_t sb = smem_u32(sm);
    int tid = threadIdx.x, lane = tid & 31, wid = tid >> 5;
    int wm = wid >> 2, wn = wid & 3;              // warp tile rows wm*64, cols wn*32
    int m0 = blockIdx.y * 128, n0 = blockIdx.x * 128;
    int kz = blockIdx.z;
    int kbase = kz * Klen;
    const float* bsel = (OUTMODE == 0 && kz) ? g_zeros : bias;
    float* csel = Cf;
    if (OUTMODE == 0) {
        if (kz == 1) csel = Cf2;
        else if (kz == 2) csel = Cf3;
        else if (kz == 3) csel = Cf4;
    }

    // ldmatrix lane offsets (row stride 144B)
    int q = lane >> 3, r = lane & 7;
    uint32_t aLane = (uint32_t)(((q & 1) * 8 + r) * GT_ROW + (q >> 1) * 16);
    uint32_t bLane = (uint32_t)(((q >> 1) * 8 + r) * GT_ROW + (q & 1) * 16);

    float acc[4][4][4];
    #pragma unroll
    for (int mi = 0; mi < 4; mi++)
        #pragma unroll
        for (int ni = 0; ni < 4; ni++)
            #pragma unroll
            for (int e = 0; e < 4; e++) acc[mi][ni][e] = 0.f;

    int nchunk = Klen >> 6;                       // K-chunk = 64

    // loader: 2 tiles x 128 rows x 8 segs of 16B = 2048 cp.async; 8 per thread
    auto load_stage = [&](int c) {
        int k0 = kbase + (c << 6);
        uint32_t base = sb + (uint32_t)(c % NSTAGE) * GT_STAGE;
        #pragma unroll
        for (int i = 0; i < 8; i++) {
            int lin = tid + i * 256;              // 0..2047
            int tsel = lin >> 10;                 // 0=Ah 1=Bh
            int within = lin & 1023;
            int row = within >> 3, seg = within & 7;
            const __half* src = (tsel == 0)
                ? Ahi + (size_t)(m0 + row) * Kfull + k0 + seg * 8
                : Bh  + (size_t)(n0 + row) * Kfull + k0 + seg * 8;
            cp_async16(base + (uint32_t)tsel * GT_TILE + (uint32_t)(row * GT_ROW + seg * 16),
                       src);
        }
    };

    load_stage(0); CP_COMMIT();
    load_stage(1); CP_COMMIT();

    for (int c = 0; c < nchunk; c++) {
        CP_WAIT(1);                 // stage c arrived
        __syncthreads();            // all warps done with stage c-1 (overwritten below)
        if (c + 2 < nchunk) load_stage(c + 2);
        CP_COMMIT();                // commit (possibly empty) keeps group count exact

        uint32_t base = sb + (uint32_t)(c % NSTAGE) * GT_STAGE;
        uint32_t aBase = base + (uint32_t)((wm * 64) * GT_ROW) + aLane;
        uint32_t bBase = base + GT_TILE + (uint32_t)((wn * 32) * GT_ROW) + bLane;

        #pragma unroll
        for (int ks = 0; ks < 4; ks++) {
            uint32_t ko = (uint32_t)(ks * 32);
            uint32_t ah[4][4], bf[2][4];
            #pragma unroll
            for (int p = 0; p < 2; p++)
                ldsm4(bf[p][0], bf[p][1], bf[p][2], bf[p][3],
                      bBase + (uint32_t)(p * 16 * GT_ROW) + ko);
            #pragma unroll
            for (int mi = 0; mi < 4; mi++)
                ldsm4(ah[mi][0], ah[mi][1], ah[mi][2], ah[mi][3],
                      aBase + (uint32_t)(mi * 16 * GT_ROW) + ko);
            #pragma unroll
            for (int mi = 0; mi < 4; mi++)
                #pragma unroll
                for (int ni = 0; ni < 4; ni++) {
                    int p = ni >> 1, su = ni & 1;
                    mma16816(acc[mi][ni], ah[mi][0], ah[mi][1], ah[mi][2], ah[mi][3],
                             bf[p][su * 2], bf[p][su * 2 + 1]);
                }
        }
    }

    // ---------------- epilogue ----------------
    int rbase = m0 + wm * 64 + (lane >> 2);
    int cbase = n0 + wn * 32 + (lane & 3) * 2;
    #pragma unroll
    for (int mi = 0; mi < 4; mi++) {
        #pragma unroll
        for (int ni = 0; ni < 4; ni++) {
            int row = rbase + mi * 16;
            int col = cbase + ni * 8;
            float b0 = bsel[col], b1 = bsel[col + 1];
            float v0 = acc[mi][ni][0] + b0, v1 = acc[mi][ni][1] + b1;
            float v2 = acc[mi][ni][2] + b0, v3 = acc[mi][ni][3] + b1;
            if (OUTMODE == 0) {
                *(float2*)(csel + (size_t)row * ldc + col)       = make_float2(v0, v1);
                *(float2*)(csel + (size_t)(row + 8) * ldc + col) = make_float2(v2, v3);
            } else {
                *(unsigned*)(Chi + (size_t)row * ldc + col) =
                    pack2h(gelu_tanh(v0), gelu_tanh(v1));
                *(unsigned*)(Chi + (size_t)(row + 8) * ldc + col) =
                    pack2h(gelu_tanh(v2), gelu_tanh(v3));
            }
        }
    }
}

// ---------------- attention: 256 threads, split j-range (QK) and d-range (PV) ----------------
#define ATTN_SMEM ((2*Ss*DHh + Ss*129 + Ss + 2*256) * (int)sizeof(float))
__global__ void __launch_bounds__(256) attn_kernel(const float* __restrict__ Qkv,
                                                   const float* __restrict__ bias,
                                                   __half* __restrict__ chi) {
    extern __shared__ float smf[];
    float* Ks = smf;                        // [128][64]
    float* Vs = smf + Ss * DHh;             // [128][64]
    float* S  = smf + 2 * Ss * DHh;         // [128][129]
    float* biasS = S + Ss * 129;            // [128]
    float* pm = biasS + Ss;                 // [256]
    float* ps = pm + 256;                   // [256]
    int bn = blockIdx.x;
    int b = bn / NHh, n = bn % NHh;
    int tid = threadIdx.x;
    int qi = tid & 127, h = tid >> 7;
    const float scale = 0.125f;

    #pragma unroll
    for (int i = 0; i < 8; i++) {
        int lin = tid + i * 256;
        int j = lin >> 4, c4 = (lin & 15) * 4;
        size_t rowb = (size_t)(b * Ss + j) * QKVN + n * DHh + c4;
        *(float4*)&Ks[j * DHh + c4] = *(const float4*)(Qkv + rowb + Hh);
        *(float4*)&Vs[j * DHh + c4] = *(const float4*)(Qkv + rowb + 2 * Hh);
    }
    if (tid < Ss) biasS[tid] = bias[b * Ss + tid];
    __syncthreads();

    float Qr[DHh];
    const float4* qp = (const float4*)(Qkv + (size_t)(b * Ss + qi) * QKVN + n * DHh);
    #pragma unroll
    for (int i = 0; i < 16; i++) {
        float4 v4 = qp[i];
        Qr[i * 4 + 0] = v4.x; Qr[i * 4 + 1] = v4.y; Qr[i * 4 + 2] = v4.z; Qr[i * 4 + 3] = v4.w;
    }

    float* Srow = S + qi * 129;
    int jbase = h * 64;
    float m = -1e30f;
    #pragma unroll 1
    for (int jj = 0; jj < 64; jj += 4) {
        int j = jbase + jj;
        const float4* k0 = (const float4*)(Ks + j * DHh);
        float s0 = 0.f, s1 = 0.f, s2 = 0.f, s3 = 0.f;
        #pragma unroll
        for (int i = 0; i < 16; i++) {
            float4 kv0 = k0[i];
            float4 kv1 = k0[16 + i];
            float4 kv2 = k0[32 + i];
            float4 kv3 = k0[48 + i];
            float q0 = Qr[i * 4], q1 = Qr[i * 4 + 1], q2 = Qr[i * 4 + 2], q3 = Qr[i * 4 + 3];
            s0 = fmaf(q0, kv0.x, s0); s0 = fmaf(q1, kv0.y, s0);
            s0 = fmaf(q2, kv0.z, s0); s0 = fmaf(q3, kv0.w, s0);
            s1 = fmaf(q0, kv1.x, s1); s1 = fmaf(q1, kv1.y, s1);
            s1 = fmaf(q2, kv1.z, s1); s1 = fmaf(q3, kv1.w, s1);
            s2 = fmaf(q0, kv2.x, s2); s2 = fmaf(q1, kv2.y, s2);
            s2 = fmaf(q2, kv2.z, s2); s2 = fmaf(q3, kv2.w, s2);
            s3 = fmaf(q0, kv3.x, s3); s3 = fmaf(q1, kv3.y, s3);
            s3 = fmaf(q2, kv3.z, s3); s3 = fmaf(q3, kv3.w, s3);
        }
        s0 = fmaf(s0, scale, biasS[j]);
        s1 = fmaf(s1, scale, biasS[j + 1]);
        s2 = fmaf(s2, scale, biasS[j + 2]);
        s3 = fmaf(s3, scale, biasS[j + 3]);
        Srow[j] = s0; Srow[j + 1] = s1; Srow[j + 2] = s2; Srow[j + 3] = s3;
        m = fmaxf(m, fmaxf(fmaxf(s0, s1), fmaxf(s2, s3)));
    }
    pm[h * 128 + qi] = m;
    __syncthreads();
    m = fmaxf(pm[qi], pm[128 + qi]);

    float ls = 0.f;
    #pragma unroll 4
    for (int jj = 0; jj < 64; jj++) {
        int j = jbase + jj;
        float p = __expf(Srow[j] - m);
        Srow[j] = p;
        ls += p;
    }
    ps[h * 128 + qi] = ls;
    __syncthreads();
    float inv_l = 1.0f / (ps[qi] + ps[128 + qi]);

    int dbase = h * 32;
    float acc[32];
    #pragma unroll
    for (int d = 0; d < 32; d++) acc[d] = 0.f;
    #pragma unroll 1
    for (int j = 0; j < Ss; j++) {
        float p = Srow[j];
        const float4* vr = (const float4*)(Vs + j * DHh + dbase);
        #pragma unroll
        for (int i = 0; i < 8; i++) {
            float4 v4 = vr[i];
            acc[i * 4 + 0] = fmaf(p, v4.x, acc[i * 4 + 0]);
            acc[i * 4 + 1] = fmaf(p, v4.y, acc[i * 4 + 1]);
            acc[i * 4 + 2] = fmaf(p, v4.z, acc[i * 4 + 2]);
            acc[i * 4 + 3] = fmaf(p, v4.w, acc[i * 4 + 3]);
        }
    }
    size_t obase = (size_t)(b * Ss + qi) * Hh + n * DHh + dbase;
    #pragma unroll
    for (int d = 0; d < 32; d += 2) {
        *(unsigned*)(chi + obase + d) = pack2h(acc[d] * inv_l, acc[d + 1] * inv_l);
    }
}

// ---------------- CLS extraction + norm ----------------
__global__ void cls_kernel() {
    __shared__ float sred[9];
    int b = blockIdx.x;
    float loc = 0.f;
    #pragma unroll
    for (int i = 0; i < 3; i++) {
        int j = threadIdx.x + i * 256;
        float v = g_x[(size_t)(b * Ss) * Hh + j];
        g_cls[b * Hh + j] = v;
        loc += v * v;
    }
    float s = blk_sum256(loc, sred);
    if (threadIdx.x == 0) g_cn[b] = fmaxf(sqrtf(s), EPS_COS);
}

__global__ void reset_best_kernel() {
    if (threadIdx.x < Bb) g_best[threadIdx.x] = 0ull;
}

// ---------------- cosine + per-block argmax reduction ----------------
__global__ void __launch_bounds__(128) cos_kernel(const float* __restrict__ lab,
                                                  float* __restrict__ out) {
    __shared__ float clsS[Bb][33];
    __shared__ float sInvCn[Bb];
    int l = blockIdx.x * 128 + threadIdx.x;
    bool valid = (l < NLl);
    if (threadIdx.x < Bb) sInvCn[threadIdx.x] = 1.0f / g_cn[threadIdx.x];

    float acc[Bb];
    #pragma unroll
    for (int bb = 0; bb < Bb; bb++) acc[bb] = 0.f;

    for (int k0 = 0; k0 < Hh; k0 += 32) {
        #pragma unroll
        for (int i = 0; i < 8; i++) {
            int idx = threadIdx.x + i * 128;
            int bb = idx >> 5, kk = idx & 31;
            clsS[bb][kk] = g_cls[bb * Hh + k0 + kk];
        }
        __syncthreads();
        if (valid) {
            float lv[32];
            const float4* lp = (const float4*)(lab + (size_t)l * Hh + k0);
            #pragma unroll
            for (int i = 0; i < 8; i++) {
                float4 v4 = lp[i];
                lv[i * 4] = v4.x; lv[i * 4 + 1] = v4.y; lv[i * 4 + 2] = v4.z; lv[i * 4 + 3] = v4.w;
            }
            #pragma unroll
            for (int bb = 0; bb < Bb; bb++) {
                float a = acc[bb];
                #pragma unroll
                for (int kk = 0; kk < 32; kk++) a = fmaf(clsS[bb][kk], lv[kk], a);
                acc[bb] = a;
            }
        }
        __syncthreads();
    }

    float invl = 0.f;
    if (valid) {
        float s = 0.f;
        const float4* lp = (const float4*)(lab + (size_t)l * Hh);
        #pragma unroll 4
        for (int i = 0; i < Hh / 4; i++) {
            float4 v4 = lp[i];
            s += v4.x * v4.x + v4.y * v4.y + v4.z * v4.z + v4.w * v4.w;
        }
        invl = 1.0f / fmaxf(sqrtf(s), EPS_COS);
    }

    int lane = threadIdx.x & 31;
    #pragma unroll 1
    for (int bb = 0; bb < Bb; bb++) {
        unsigned long long key = 0ull;
        if (valid) {
            float c = acc[bb] * invl * sInvCn[bb];
            out[(size_t)bb * NLl + l] = c;
            key = pack_key(c, l);
        }
        #pragma unroll
        for (int o = 16; o > 0; o >>= 1) {
            unsigned long long other = __shfl_down_sync(0xffffffffu, key, o);
            key = (other > key) ? other : key;
        }
        if (lane == 0) atomicMax(&g_best[bb], key);
    }
}

__global__ void ids_out_kernel(float* __restrict__ out) {
    int b = threadIdx.x;
    if (b < Bb) {
        unsigned idpart = (unsigned)(g_best[b] & 0xFFFFFFFFull);
        out[(size_t)Bb * NLl + b] = (float)(0xFFFFFFFFu - idpart);
    }
}

// ---------------- host orchestration ----------------
extern "C" void kernel_launch(void* const* d_in, const int* in_sizes, int n_in,
                              void* d_out, int out_size) {
    const int*   ids  = (const int*)d_in[0];
    const int*   tys  = (const int*)d_in[1];
    const float* word = (const float*)d_in[2];
    const float* pos  = (const float*)d_in[3];
    const float* typ  = (const float*)d_in[4];
    const float* eg   = (const float*)d_in[5];
    const float* eb   = (const float*)d_in[6];
    const float* Wq   = (const float*)d_in[7];
    const float* bq   = (const float*)d_in[8];
    const float* Wk   = (const float*)d_in[9];
    const float* bk   = (const float*)d_in[10];
    const float* Wv   = (const float*)d_in[11];
    const float* bv   = (const float*)d_in[12];
    const float* Wo   = (const float*)d_in[13];
    const float* bo   = (const float*)d_in[14];
    const float* g1   = (const float*)d_in[15];
    const float* be1  = (const float*)d_in[16];
    const float* W1   = (const float*)d_in[17];
    const float* b1   = (const float*)d_in[18];
    const float* W2   = (const float*)d_in[19];
    const float* b2   = (const float*)d_in[20];
    const float* g2   = (const float*)d_in[21];
    const float* be2  = (const float*)d_in[22];
    const float* lab  = (const float*)d_in[23];
    float* out = (float*)d_out;

    float *px, *py, *py2, *py3, *py4, *pqkv, *pmbias, *pbqkv;
    __half *pxhi, *pchi, *phhi, *pwth;
    cudaGetSymbolAddress((void**)&px,    g_x);
    cudaGetSymbolAddress((void**)&py,    g_y);
    cudaGetSymbolAddress((void**)&py2,   g_y2);
    cudaGetSymbolAddress((void**)&py3,   g_y3);
    cudaGetSymbolAddress((void**)&py4,   g_y4);
    cudaGetSymbolAddress((void**)&pqkv,  g_qkv);
    cudaGetSymbolAddress((void**)&pmbias,g_mbias);
    cudaGetSymbolAddress((void**)&pbqkv, g_bqkv);
    cudaGetSymbolAddress((void**)&pxhi,  g_xhi);
    cudaGetSymbolAddress((void**)&pchi,  g_chi);
    cudaGetSymbolAddress((void**)&phhi,  g_hhi);
    cudaGetSymbolAddress((void**)&pwth,  g_wth);

    cudaFuncSetAttribute(attn_kernel, cudaFuncAttributeMaxDynamicSharedMemorySize, ATTN_SMEM);
    cudaFuncSetAttribute(gemm_mma<0>, cudaFuncAttributeMaxDynamicSharedMemorySize, GSMEM);
    cudaFuncSetAttribute(gemm_mma<1>, cudaFuncAttributeMaxDynamicSharedMemorySize, GSMEM);

    dim3 tb(32, 8);
    wsplit4_kernel<<<dim3(24, 24, 48), tb>>>(Wq, Wk, Wv, Wo);                 // 1
    embed_ln_kernel<<<NTOK, 256>>>(ids, tys, word, pos, typ, eg, eb);         // 2
    pack_bias_kernel<<<Ll, Hh>>>(bq, bk, bv);                                 // 3

    for (int l = 0; l < Ll; l++) {
        size_t wl = (size_t)l * LSTRIDE;
        // QKV
        gemm_mma<0><<<dim3(QKVN / 128, 32, 1), 256, GSMEM>>>(                 // 4 on l==0
            pxhi, pwth + wl, pbqkv + l * QKVN,
            pqkv, nullptr, nullptr, nullptr, nullptr, Hh, Hh, QKVN);
        attn_kernel<<<Bb * NHh, 256, ATTN_SMEM>>>(pqkv, pmbias, pchi);
        if (l == 0) {
            wsplit_kernel<<<dim3(FFf / 32, Hh / 32, Ll), tb>>>(W1, OFF_W1, Hh, FFf);
            wsplit_kernel<<<dim3(Hh / 32, FFf / 32, Ll), tb>>>(W2, OFF_W2, FFf, Hh);
        }
        // O projection: split-K=2
        gemm_mma<0><<<dim3(Hh / 128, 32, 2), 256, GSMEM>>>(
            pchi, pwth + wl + OFF_O, bo + (size_t)l * Hh,
            py, py2, nullptr, nullptr, nullptr, Hh, Hh / 2, Hh);
        add_ln3_kernel<<<NTOK, 256>>>(px, py, py2,
                                      g1 + (size_t)l * Hh, be1 + (size_t)l * Hh);
        // FFN up + GELU
        gemm_mma<1><<<dim3(FFf / 128, 32, 1), 256, GSMEM>>>(
            pxhi, pwth + wl + OFF_W1, b1 + (size_t)l * FFf,
            nullptr, nullptr, nullptr, nullptr, phhi, Hh, Hh, FFf);
        // FFN down: split-K=4
        gemm_mma<0><<<dim3(Hh / 128, 32, 4), 256, GSMEM>>>(
            phhi, pwth + wl + OFF_W2, b2 + (size_t)l * Hh,
            py, py2, py3, py4, nullptr, FFf, FFf / 4, Hh);
        add_ln5_kernel<<<NTOK, 256>>>(px, py, py2, py3, py4,
                                      g2 + (size_t)l * Hh, be2 + (size_t)l * Hh);
    }

    cls_kernel<<<Bb, 256>>>();
    reset_best_kernel<<<1, 32>>>();
    cos_kernel<<<(NLl + 127) / 128, 128>>>(lab, out);
    if (out_size >= Bb * NLl + Bb) ids_out_kernel<<<1, 32>>>(out);
}

// round 15
// speedup vs baseline: 1.0311x; 1.0311x over previous
#include <cuda_runtime.h>
#include <cuda_fp16.h>
#include <math.h>
#include <cstdint>

// ---------------- problem constants ----------------
#define Vv   30522
#define Hh   768
#define Ll   12
#define FFf  3072
#define NHh  12
#define DHh  64
#define Bb   32
#define Ss   128
#define NLl  10000
#define NTOK (Bb*Ss)          // 4096
#define QKVN (3*Hh)           // 2304
#define EPS_LN  1e-12f
#define EPS_COS 1e-8f

// transposed fp16 weight layout per layer (element offsets)
#define OFF_O   (QKVN*Hh)             // after packed qkv [2304][768]
#define OFF_W1  (OFF_O + Hh*Hh)       // [3072][768]
#define OFF_W2  (OFF_W1 + Hh*FFf)     // [768][3072]
#define LSTRIDE (OFF_W2 + FFf*Hh)     // 7,077,888

// ---------------- device scratch ----------------
__device__ __half g_wth[Ll*LSTRIDE];           // fp16 weights, transposed [N][K]
__device__ float  g_bqkv[Ll*QKVN];
__device__ float  g_zeros[Hh];                 // stays zero (module-load zero-init)

__device__ float  g_x  [NTOK*Hh];
__device__ __half g_xhi[NTOK*Hh];
__device__ float  g_qkv[NTOK*QKVN];
__device__ __half g_chi[NTOK*Hh];
__device__ __half g_hhi[NTOK*FFf];
__device__ float  g_y  [NTOK*Hh];
__device__ float  g_y2 [NTOK*Hh];
__device__ float  g_y3 [NTOK*Hh];
__device__ float g_mbias[NTOK];
__device__ float g_cls[Bb*Hh];
__device__ float g_cn [Bb];
__device__ unsigned long long g_best[Bb];

// ---------------- PTX helpers (compute_100-safe) ----------------
__device__ __forceinline__ uint32_t smem_u32(const void* p) {
    uint32_t a;
    asm("{ .reg .u64 t; cvta.to.shared.u64 t, %1; cvt.u32.u64 %0, t; }" : "=r"(a) : "l"(p));
    return a;
}
__device__ __forceinline__ void cp_async16(uint32_t dst, const void* src) {
    asm volatile("cp.async.cg.shared.global [%0], [%1], 16;" :: "r"(dst), "l"(src) : "memory");
}
#define CP_COMMIT() asm volatile("cp.async.commit_group;" ::: "memory")
#define CP_WAIT(n)  asm volatile("cp.async.wait_group %0;" :: "n"(n) : "memory")

__device__ __forceinline__ void ldsm4(uint32_t& r0, uint32_t& r1, uint32_t& r2, uint32_t& r3,
                                      uint32_t addr) {
    asm volatile("ldmatrix.sync.aligned.m8n8.x4.shared.b16 {%0,%1,%2,%3}, [%4];"
                 : "=r"(r0), "=r"(r1), "=r"(r2), "=r"(r3) : "r"(addr));
}
__device__ __forceinline__ void mma16816(float* c, uint32_t a0, uint32_t a1, uint32_t a2,
                                         uint32_t a3, uint32_t b0, uint32_t b1) {
    asm volatile(
        "mma.sync.aligned.m16n8k16.row.col.f32.f16.f16.f32 "
        "{%0,%1,%2,%3}, {%4,%5,%6,%7}, {%8,%9}, {%0,%1,%2,%3};"
        : "+f"(c[0]), "+f"(c[1]), "+f"(c[2]), "+f"(c[3])
        : "r"(a0), "r"(a1), "r"(a2), "r"(a3), "r"(b0), "r"(b1));
}

// ---------------- misc helpers ----------------
__device__ __forceinline__ float blk_sum256(float v, volatile float* sred) {
    int lane = threadIdx.x & 31, w = threadIdx.x >> 5;
    #pragma unroll
    for (int o = 16; o > 0; o >>= 1) v += __shfl_down_sync(0xffffffffu, v, o);
    if (lane == 0) sred[w] = v;
    __syncthreads();
    if (threadIdx.x == 0) {
        float s = 0.f;
        #pragma unroll
        for (int i = 0; i < 8; i++) s += sred[i];
        sred[8] = s;
    }
    __syncthreads();
    float r = sred[8];
    __syncthreads();
    return r;
}
__device__ __forceinline__ float gelu_tanh(float x) {
    float x3 = x * x * x;
    float t = tanhf(0.7978845608028654f * (x + 0.044715f * x3));
    return 0.5f * x * (1.0f + t);
}
__device__ __forceinline__ unsigned long long pack_key(float c, int l) {
    unsigned u = __float_as_uint(c);
    u = (u & 0x80000000u) ? ~u : (u | 0x80000000u);
    return ((unsigned long long)u << 32) | (unsigned long long)(0xFFFFFFFFu - (unsigned)l);
}
__device__ __forceinline__ unsigned pack2h(float v0, float v1) {
    __half h0 = __float2half(v0), h1 = __float2half(v1);
    return (unsigned)__half_as_ushort(h0) | ((unsigned)__half_as_ushort(h1) << 16);
}

// ---------------- weight transpose to fp16 ----------------
__global__ void wsplit4_kernel(const float* __restrict__ W0, const float* __restrict__ W1m,
                               const float* __restrict__ W2m, const float* __restrict__ W3m) {
    __shared__ float t[32][33];
    int z = blockIdx.z;
    int m = z & 3, l = z >> 2;
    const float* Ws = (m == 0 ? W0 : m == 1 ? W1m : m == 2 ? W2m : W3m) + (size_t)l * Hh * Hh;
    long dstOff = (m < 3) ? (long)m * Hh * Hh : (long)OFF_O;
    __half* th = g_wth + (size_t)l * LSTRIDE + dstOff;
    int n = blockIdx.x * 32 + threadIdx.x;
    #pragma unroll
    for (int i = 0; i < 4; i++) {
        int k = blockIdx.y * 32 + threadIdx.y + i * 8;
        t[threadIdx.y + i * 8][threadIdx.x] = Ws[(size_t)k * Hh + n];
    }
    __syncthreads();
    int k2 = blockIdx.y * 32 + threadIdx.x;
    #pragma unroll
    for (int i = 0; i < 4; i++) {
        int n2 = blockIdx.x * 32 + threadIdx.y + i * 8;
        th[(size_t)n2 * Hh + k2] = __float2half(t[threadIdx.x][threadIdx.y + i * 8]);
    }
}

__global__ void wsplit_kernel(const float* __restrict__ W, long dstOff, int K, int N) {
    __shared__ float t[32][33];
    int l = blockIdx.z;
    const float* Ws = W + (size_t)l * K * N;
    __half* th = g_wth + (size_t)l * LSTRIDE + dstOff;
    int n = blockIdx.x * 32 + threadIdx.x;
    #pragma unroll
    for (int i = 0; i < 4; i++) {
        int k = blockIdx.y * 32 + threadIdx.y + i * 8;
        t[threadIdx.y + i * 8][threadIdx.x] = Ws[(size_t)k * N + n];
    }
    __syncthreads();
    int k2 = blockIdx.y * 32 + threadIdx.x;
    #pragma unroll
    for (int i = 0; i < 4; i++) {
        int n2 = blockIdx.x * 32 + threadIdx.y + i * 8;
        th[(size_t)n2 * K + k2] = __float2half(t[threadIdx.x][threadIdx.y + i * 8]);
    }
}

__global__ void pack_bias_kernel(const float* __restrict__ bq, const float* __restrict__ bk,
                                 const float* __restrict__ bv) {
    int l = blockIdx.x, j = threadIdx.x;
    g_bqkv[l * QKVN + j]          = bq[l * Hh + j];
    g_bqkv[l * QKVN + Hh + j]     = bk[l * Hh + j];
    g_bqkv[l * QKVN + 2 * Hh + j] = bv[l * Hh + j];
}

// ---------------- embeddings + LN + mask bias ----------------
__global__ void embed_ln_kernel(const int* __restrict__ ids, const int* __restrict__ tys,
                                const float* __restrict__ word, const float* __restrict__ pos,
                                const float* __restrict__ typ,
                                const float* __restrict__ eg, const float* __restrict__ eb) {
    __shared__ float sred[9];
    int t = blockIdx.x;
    int s = t & (Ss - 1);
    int id = ids[t], ty = tys[t];
    float v[3];
    float loc = 0.f;
    #pragma unroll
    for (int i = 0; i < 3; i++) {
        int j = threadIdx.x + i * 256;
        v[i] = word[(size_t)id * Hh + j] + pos[(size_t)s * Hh + j] + typ[(size_t)ty * Hh + j];
        loc += v[i];
    }
    float mu = blk_sum256(loc, sred) * (1.0f / Hh);
    float l2 = 0.f;
    #pragma unroll
    for (int i = 0; i < 3; i++) { float d = v[i] - mu; l2 += d * d; }
    float var = blk_sum256(l2, sred) * (1.0f / Hh);
    float rstd = rsqrtf(var + EPS_LN);
    #pragma unroll
    for (int i = 0; i < 3; i++) {
        int j = threadIdx.x + i * 256;
        size_t idx = (size_t)t * Hh + j;
        float o = (v[i] - mu) * rstd * eg[j] + eb[j];
        g_x[idx] = o;
        g_xhi[idx] = __float2half(o);
    }
    if (threadIdx.x == 0) g_mbias[t] = (id > 0) ? 0.f : -10000.0f;
}

// ---------------- residual add (3-way) + LN ----------------
__global__ void add_ln3_kernel(float* __restrict__ x, const float* __restrict__ y,
                               const float* __restrict__ y2,
                               const float* __restrict__ g, const float* __restrict__ b) {
    __shared__ float sred[9];
    size_t base = (size_t)blockIdx.x * Hh;
    float v[3];
    float loc = 0.f;
    #pragma unroll
    for (int i = 0; i < 3; i++) {
        int j = threadIdx.x + i * 256;
        v[i] = x[base + j] + y[base + j] + y2[base + j];
        loc += v[i];
    }
    float mu = blk_sum256(loc, sred) * (1.0f / Hh);
    float l2 = 0.f;
    #pragma unroll
    for (int i = 0; i < 3; i++) { float d = v[i] - mu; l2 += d * d; }
    float var = blk_sum256(l2, sred) * (1.0f / Hh);
    float rstd = rsqrtf(var + EPS_LN);
    #pragma unroll
    for (int i = 0; i < 3; i++) {
        int j = threadIdx.x + i * 256;
        float o = (v[i] - mu) * rstd * g[j] + b[j];
        x[base + j] = o;
        g_xhi[base + j] = __float2half(o);
    }
}

// ---------------- residual add (4-way) + LN (for split-K3 W2) ----------------
__global__ void add_ln4_kernel(float* __restrict__ x, const float* __restrict__ y,
                               const float* __restrict__ y2, const float* __restrict__ y3,
                               const float* __restrict__ g, const float* __restrict__ b) {
    __shared__ float sred[9];
    size_t base = (size_t)blockIdx.x * Hh;
    float v[3];
    float loc = 0.f;
    #pragma unroll
    for (int i = 0; i < 3; i++) {
        int j = threadIdx.x + i * 256;
        v[i] = x[base + j] + y[base + j] + y2[base + j] + y3[base + j];
        loc += v[i];
    }
    float mu = blk_sum256(loc, sred) * (1.0f / Hh);
    float l2 = 0.f;
    #pragma unroll
    for (int i = 0; i < 3; i++) { float d = v[i] - mu; l2 += d * d; }
    float var = blk_sum256(l2, sred) * (1.0f / Hh);
    float rstd = rsqrtf(var + EPS_LN);
    #pragma unroll
    for (int i = 0; i < 3; i++) {
        int j = threadIdx.x + i * 256;
        float o = (v[i] - mu) * rstd * g[j] + b[j];
        x[base + j] = o;
        g_xhi[base + j] = __float2half(o);
    }
}

// ---------------- HMMA fp16 GEMM: C[4096, N] = Ah @ Bh^T + bias ----------------
// K-split via gridDim.z (OUTMODE 0): z=0 -> Cf with bias, z>=1 -> Cfz zero-bias.
// OUTMODE 1: gelu -> fp16 out. CTA 128x128, K-chunk 64 (rows 144B), 2-stage
// cp.async, 8 warps, 2 CTAs/SM.
#define GT_ROW   144
#define GT_TILE  (128 * GT_ROW)        // 18432 B per sub-tile
#define GT_STAGE (2 * GT_TILE)         // Ah | Bh = 36864
#define GSMEM    (2 * GT_STAGE)        // 73728
template <int OUTMODE>
__global__ void __launch_bounds__(256, 2) gemm_mma(
    const __half* __restrict__ Ahi,
    const __half* __restrict__ Bh,
    const float* __restrict__ bias,
    float* __restrict__ Cf, float* __restrict__ Cf2, float* __restrict__ Cf3,
    __half* __restrict__ Chi,
    int Kfull, int Klen, int ldc)
{
    extern __shared__ char sm[];
    const uint32_t sb = smem_u32(sm);
    int tid = threadIdx.x, lane = tid & 31, wid = tid >> 5;
    int wm = wid >> 2, wn = wid & 3;              // warp tile rows wm*64, cols wn*32
    int m0 = blockIdx.y * 128, n0 = blockIdx.x * 128;
    int kz = blockIdx.z;
    int kbase = kz * Klen;
    const float* bsel = (OUTMODE == 0 && kz) ? g_zeros : bias;
    float* csel = Cf;
    if (OUTMODE == 0) {
        if (kz == 1) csel = Cf2;
        else if (kz == 2) csel = Cf3;
    }

    // ldmatrix lane offsets (row stride 144B)
    int q = lane >> 3, r = lane & 7;
    uint32_t aLane = (uint32_t)(((q & 1) * 8 + r) * GT_ROW + (q >> 1) * 16);
    uint32_t bLane = (uint32_t)(((q >> 1) * 8 + r) * GT_ROW + (q & 1) * 16);

    float acc[4][4][4];
    #pragma unroll
    for (int mi = 0; mi < 4; mi++)
        #pragma unroll
        for (int ni = 0; ni < 4; ni++)
            #pragma unroll
            for (int e = 0; e < 4; e++) acc[mi][ni][e] = 0.f;

    int nchunk = Klen >> 6;                       // K-chunk = 64

    // loader: 2 tiles x 128 rows x 8 segs of 16B = 2048 cp.async; 8 per thread
    auto load_stage = [&](int c) {
        int k0 = kbase + (c << 6);
        uint32_t base = sb + (uint32_t)(c & 1) * GT_STAGE;
        #pragma unroll
        for (int i = 0; i < 8; i++) {
            int lin = tid + i * 256;              // 0..2047
            int tsel = lin >> 10;                 // 0=Ah 1=Bh
            int within = lin & 1023;
            int row = within >> 3, seg = within & 7;
            const __half* src = (tsel == 0)
                ? Ahi + (size_t)(m0 + row) * Kfull + k0 + seg * 8
                : Bh  + (size_t)(n0 + row) * Kfull + k0 + seg * 8;
            cp_async16(base + (uint32_t)tsel * GT_TILE + (uint32_t)(row * GT_ROW + seg * 16),
                       src);
        }
    };

    load_stage(0);
    CP_COMMIT();

    for (int c = 0; c < nchunk; c++) {
        if (c + 1 < nchunk) { load_stage(c + 1); CP_COMMIT(); CP_WAIT(1); }
        else { CP_WAIT(0); }
        __syncthreads();

        uint32_t base = sb + (uint32_t)(c & 1) * GT_STAGE;
        uint32_t aBase = base + (uint32_t)((wm * 64) * GT_ROW) + aLane;
        uint32_t bBase = base + GT_TILE + (uint32_t)((wn * 32) * GT_ROW) + bLane;

        #pragma unroll
        for (int ks = 0; ks < 4; ks++) {
            uint32_t ko = (uint32_t)(ks * 32);
            uint32_t ah[4][4], bf[2][4];
            #pragma unroll
            for (int p = 0; p < 2; p++)
                ldsm4(bf[p][0], bf[p][1], bf[p][2], bf[p][3],
                      bBase + (uint32_t)(p * 16 * GT_ROW) + ko);
            #pragma unroll
            for (int mi = 0; mi < 4; mi++)
                ldsm4(ah[mi][0], ah[mi][1], ah[mi][2], ah[mi][3],
                      aBase + (uint32_t)(mi * 16 * GT_ROW) + ko);
            #pragma unroll
            for (int mi = 0; mi < 4; mi++)
                #pragma unroll
                for (int ni = 0; ni < 4; ni++) {
                    int p = ni >> 1, su = ni & 1;
                    mma16816(acc[mi][ni], ah[mi][0], ah[mi][1], ah[mi][2], ah[mi][3],
                             bf[p][su * 2], bf[p][su * 2 + 1]);
                }
        }
        __syncthreads();
    }

    // ---------------- epilogue ----------------
    int rbase = m0 + wm * 64 + (lane >> 2);
    int cbase = n0 + wn * 32 + (lane & 3) * 2;
    #pragma unroll
    for (int mi = 0; mi < 4; mi++) {
        #pragma unroll
        for (int ni = 0; ni < 4; ni++) {
            int row = rbase + mi * 16;
            int col = cbase + ni * 8;
            float b0 = bsel[col], b1 = bsel[col + 1];
            float v0 = acc[mi][ni][0] + b0, v1 = acc[mi][ni][1] + b1;
            float v2 = acc[mi][ni][2] + b0, v3 = acc[mi][ni][3] + b1;
            if (OUTMODE == 0) {
                *(float2*)(csel + (size_t)row * ldc + col)       = make_float2(v0, v1);
                *(float2*)(csel + (size_t)(row + 8) * ldc + col) = make_float2(v2, v3);
            } else {
                *(unsigned*)(Chi + (size_t)row * ldc + col) =
                    pack2h(gelu_tanh(v0), gelu_tanh(v1));
                *(unsigned*)(Chi + (size_t)(row + 8) * ldc + col) =
                    pack2h(gelu_tanh(v2), gelu_tanh(v3));
            }
        }
    }
}

// ---------------- attention: 256 threads, split j-range (QK) and d-range (PV) ----------------
#define ATTN_SMEM ((2*Ss*DHh + Ss*129 + Ss + 2*256) * (int)sizeof(float))
__global__ void __launch_bounds__(256) attn_kernel(const float* __restrict__ Qkv,
                                                   const float* __restrict__ bias,
                                                   __half* __restrict__ chi) {
    extern __shared__ float smf[];
    float* Ks = smf;                        // [128][64]
    float* Vs = smf + Ss * DHh;             // [128][64]
    float* S  = smf + 2 * Ss * DHh;         // [128][129]
    float* biasS = S + Ss * 129;            // [128]
    float* pm = biasS + Ss;                 // [256]
    float* ps = pm + 256;                   // [256]
    int bn = blockIdx.x;
    int b = bn / NHh, n = bn % NHh;
    int tid = threadIdx.x;
    int qi = tid & 127, h = tid >> 7;
    const float scale = 0.125f;

    #pragma unroll
    for (int i = 0; i < 8; i++) {
        int lin = tid + i * 256;
        int j = lin >> 4, c4 = (lin & 15) * 4;
        size_t rowb = (size_t)(b * Ss + j) * QKVN + n * DHh + c4;
        *(float4*)&Ks[j * DHh + c4] = *(const float4*)(Qkv + rowb + Hh);
        *(float4*)&Vs[j * DHh + c4] = *(const float4*)(Qkv + rowb + 2 * Hh);
    }
    if (tid < Ss) biasS[tid] = bias[b * Ss + tid];
    __syncthreads();

    float Qr[DHh];
    const float4* qp = (const float4*)(Qkv + (size_t)(b * Ss + qi) * QKVN + n * DHh);
    #pragma unroll
    for (int i = 0; i < 16; i++) {
        float4 v4 = qp[i];
        Qr[i * 4 + 0] = v4.x; Qr[i * 4 + 1] = v4.y; Qr[i * 4 + 2] = v4.z; Qr[i * 4 + 3] = v4.w;
    }

    float* Srow = S + qi * 129;
    int jbase = h * 64;
    float m = -1e30f;
    #pragma unroll 1
    for (int jj = 0; jj < 64; jj += 4) {
        int j = jbase + jj;
        const float4* k0 = (const float4*)(Ks + j * DHh);
        float s0 = 0.f, s1 = 0.f, s2 = 0.f, s3 = 0.f;
        #pragma unroll
        for (int i = 0; i < 16; i++) {
            float4 kv0 = k0[i];
            float4 kv1 = k0[16 + i];
            float4 kv2 = k0[32 + i];
            float4 kv3 = k0[48 + i];
            float q0 = Qr[i * 4], q1 = Qr[i * 4 + 1], q2 = Qr[i * 4 + 2], q3 = Qr[i * 4 + 3];
            s0 = fmaf(q0, kv0.x, s0); s0 = fmaf(q1, kv0.y, s0);
            s0 = fmaf(q2, kv0.z, s0); s0 = fmaf(q3, kv0.w, s0);
            s1 = fmaf(q0, kv1.x, s1); s1 = fmaf(q1, kv1.y, s1);
            s1 = fmaf(q2, kv1.z, s1); s1 = fmaf(q3, kv1.w, s1);
            s2 = fmaf(q0, kv2.x, s2); s2 = fmaf(q1, kv2.y, s2);
            s2 = fmaf(q2, kv2.z, s2); s2 = fmaf(q3, kv2.w, s2);
            s3 = fmaf(q0, kv3.x, s3); s3 = fmaf(q1, kv3.y, s3);
            s3 = fmaf(q2, kv3.z, s3); s3 = fmaf(q3, kv3.w, s3);
        }
        s0 = fmaf(s0, scale, biasS[j]);
        s1 = fmaf(s1, scale, biasS[j + 1]);
        s2 = fmaf(s2, scale, biasS[j + 2]);
        s3 = fmaf(s3, scale, biasS[j + 3]);
        Srow[j] = s0; Srow[j + 1] = s1; Srow[j + 2] = s2; Srow[j + 3] = s3;
        m = fmaxf(m, fmaxf(fmaxf(s0, s1), fmaxf(s2, s3)));
    }
    pm[h * 128 + qi] = m;
    __syncthreads();
    m = fmaxf(pm[qi], pm[128 + qi]);

    float ls = 0.f;
    #pragma unroll 4
    for (int jj = 0; jj < 64; jj++) {
        int j = jbase + jj;
        float p = __expf(Srow[j] - m);
        Srow[j] = p;
        ls += p;
    }
    ps[h * 128 + qi] = ls;
    __syncthreads();
    float inv_l = 1.0f / (ps[qi] + ps[128 + qi]);

    int dbase = h * 32;
    float acc[32];
    #pragma unroll
    for (int d = 0; d < 32; d++) acc[d] = 0.f;
    #pragma unroll 1
    for (int j = 0; j < Ss; j++) {
        float p = Srow[j];
        const float4* vr = (const float4*)(Vs + j * DHh + dbase);
        #pragma unroll
        for (int i = 0; i < 8; i++) {
            float4 v4 = vr[i];
            acc[i * 4 + 0] = fmaf(p, v4.x, acc[i * 4 + 0]);
            acc[i * 4 + 1] = fmaf(p, v4.y, acc[i * 4 + 1]);
            acc[i * 4 + 2] = fmaf(p, v4.z, acc[i * 4 + 2]);
            acc[i * 4 + 3] = fmaf(p, v4.w, acc[i * 4 + 3]);
        }
    }
    size_t obase = (size_t)(b * Ss + qi) * Hh + n * DHh + dbase;
    #pragma unroll
    for (int d = 0; d < 32; d += 2) {
        *(unsigned*)(chi + obase + d) = pack2h(acc[d] * inv_l, acc[d + 1] * inv_l);
    }
}

// ---------------- CLS extraction + norm ----------------
__global__ void cls_kernel() {
    __shared__ float sred[9];
    int b = blockIdx.x;
    float loc = 0.f;
    #pragma unroll
    for (int i = 0; i < 3; i++) {
        int j = threadIdx.x + i * 256;
        float v = g_x[(size_t)(b * Ss) * Hh + j];
        g_cls[b * Hh + j] = v;
        loc += v * v;
    }
    float s = blk_sum256(loc, sred);
    if (threadIdx.x == 0) g_cn[b] = fmaxf(sqrtf(s), EPS_COS);
}

__global__ void reset_best_kernel() {
    if (threadIdx.x < Bb) g_best[threadIdx.x] = 0ull;
}

// ---------------- cosine + per-block argmax reduction ----------------
__global__ void __launch_bounds__(128) cos_kernel(const float* __restrict__ lab,
                                                  float* __restrict__ out) {
    __shared__ float clsS[Bb][33];
    __shared__ float sInvCn[Bb];
    int l = blockIdx.x * 128 + threadIdx.x;
    bool valid = (l < NLl);
    if (threadIdx.x < Bb) sInvCn[threadIdx.x] = 1.0f / g_cn[threadIdx.x];

    float acc[Bb];
    #pragma unroll
    for (int bb = 0; bb < Bb; bb++) acc[bb] = 0.f;

    for (int k0 = 0; k0 < Hh; k0 += 32) {
        #pragma unroll
        for (int i = 0; i < 8; i++) {
            int idx = threadIdx.x + i * 128;
            int bb = idx >> 5, kk = idx & 31;
            clsS[bb][kk] = g_cls[bb * Hh + k0 + kk];
        }
        __syncthreads();
        if (valid) {
            float lv[32];
            const float4* lp = (const float4*)(lab + (size_t)l * Hh + k0);
            #pragma unroll
            for (int i = 0; i < 8; i++) {
                float4 v4 = lp[i];
                lv[i * 4] = v4.x; lv[i * 4 + 1] = v4.y; lv[i * 4 + 2] = v4.z; lv[i * 4 + 3] = v4.w;
            }
            #pragma unroll
            for (int bb = 0; bb < Bb; bb++) {
                float a = acc[bb];
                #pragma unroll
                for (int kk = 0; kk < 32; kk++) a = fmaf(clsS[bb][kk], lv[kk], a);
                acc[bb] = a;
            }
        }
        __syncthreads();
    }

    float invl = 0.f;
    if (valid) {
        float s = 0.f;
        const float4* lp = (const float4*)(lab + (size_t)l * Hh);
        #pragma unroll 4
        for (int i = 0; i < Hh / 4; i++) {
            float4 v4 = lp[i];
            s += v4.x * v4.x + v4.y * v4.y + v4.z * v4.z + v4.w * v4.w;
        }
        invl = 1.0f / fmaxf(sqrtf(s), EPS_COS);
    }

    int lane = threadIdx.x & 31;
    #pragma unroll 1
    for (int bb = 0; bb < Bb; bb++) {
        unsigned long long key = 0ull;
        if (valid) {
            float c = acc[bb] * invl * sInvCn[bb];
            out[(size_t)bb * NLl + l] = c;
            key = pack_key(c, l);
        }
        #pragma unroll
        for (int o = 16; o > 0; o >>= 1) {
            unsigned long long other = __shfl_down_sync(0xffffffffu, key, o);
            key = (other > key) ? other : key;
        }
        if (lane == 0) atomicMax(&g_best[bb], key);
    }
}

__global__ void ids_out_kernel(float* __restrict__ out) {
    int b = threadIdx.x;
    if (b < Bb) {
        unsigned idpart = (unsigned)(g_best[b] & 0xFFFFFFFFull);
        out[(size_t)Bb * NLl + b] = (float)(0xFFFFFFFFu - idpart);
    }
}

// ---------------- host orchestration ----------------
extern "C" void kernel_launch(void* const* d_in, const int* in_sizes, int n_in,
                              void* d_out, int out_size) {
    const int*   ids  = (const int*)d_in[0];
    const int*   tys  = (const int*)d_in[1];
    const float* word = (const float*)d_in[2];
    const float* pos  = (const float*)d_in[3];
    const float* typ  = (const float*)d_in[4];
    const float* eg   = (const float*)d_in[5];
    const float* eb   = (const float*)d_in[6];
    const float* Wq   = (const float*)d_in[7];
    const float* bq   = (const float*)d_in[8];
    const float* Wk   = (const float*)d_in[9];
    const float* bk   = (const float*)d_in[10];
    const float* Wv   = (const float*)d_in[11];
    const float* bv   = (const float*)d_in[12];
    const float* Wo   = (const float*)d_in[13];
    const float* bo   = (const float*)d_in[14];
    const float* g1   = (const float*)d_in[15];
    const float* be1  = (const float*)d_in[16];
    const float* W1   = (const float*)d_in[17];
    const float* b1   = (const float*)d_in[18];
    const float* W2   = (const float*)d_in[19];
    const float* b2   = (const float*)d_in[20];
    const float* g2   = (const float*)d_in[21];
    const float* be2  = (const float*)d_in[22];
    const float* lab  = (const float*)d_in[23];
    float* out = (float*)d_out;

    float *px, *py, *py2, *py3, *pqkv, *pmbias, *pbqkv;
    __half *pxhi, *pchi, *phhi, *pwth;
    cudaGetSymbolAddress((void**)&px,    g_x);
    cudaGetSymbolAddress((void**)&py,    g_y);
    cudaGetSymbolAddress((void**)&py2,   g_y2);
    cudaGetSymbolAddress((void**)&py3,   g_y3);
    cudaGetSymbolAddress((void**)&pqkv,  g_qkv);
    cudaGetSymbolAddress((void**)&pmbias,g_mbias);
    cudaGetSymbolAddress((void**)&pbqkv, g_bqkv);
    cudaGetSymbolAddress((void**)&pxhi,  g_xhi);
    cudaGetSymbolAddress((void**)&pchi,  g_chi);
    cudaGetSymbolAddress((void**)&phhi,  g_hhi);
    cudaGetSymbolAddress((void**)&pwth,  g_wth);

    cudaFuncSetAttribute(attn_kernel, cudaFuncAttributeMaxDynamicSharedMemorySize, ATTN_SMEM);
    cudaFuncSetAttribute(gemm_mma<0>, cudaFuncAttributeMaxDynamicSharedMemorySize, GSMEM);
    cudaFuncSetAttribute(gemm_mma<1>, cudaFuncAttributeMaxDynamicSharedMemorySize, GSMEM);

    dim3 tb(32, 8);
    wsplit4_kernel<<<dim3(24, 24, 48), tb>>>(Wq, Wk, Wv, Wo);                 // 1
    embed_ln_kernel<<<NTOK, 256>>>(ids, tys, word, pos, typ, eg, eb);         // 2
    pack_bias_kernel<<<Ll, Hh>>>(bq, bk, bv);                                 // 3

    for (int l = 0; l < Ll; l++) {
        size_t wl = (size_t)l * LSTRIDE;
        // QKV
        gemm_mma<0><<<dim3(QKVN / 128, 32, 1), 256, GSMEM>>>(                 // 4 on l==0
            pxhi, pwth + wl, pbqkv + l * QKVN,
            pqkv, nullptr, nullptr, nullptr, Hh, Hh, QKVN);
        attn_kernel<<<Bb * NHh, 256, ATTN_SMEM>>>(pqkv, pmbias, pchi);
        if (l == 0) {
            wsplit_kernel<<<dim3(FFf / 32, Hh / 32, Ll), tb>>>(W1, OFF_W1, Hh, FFf);
            wsplit_kernel<<<dim3(Hh / 32, FFf / 32, Ll), tb>>>(W2, OFF_W2, FFf, Hh);
        }
        // O projection: split-K=2
        gemm_mma<0><<<dim3(Hh / 128, 32, 2), 256, GSMEM>>>(
            pchi, pwth + wl + OFF_O, bo + (size_t)l * Hh,
            py, py2, nullptr, nullptr, Hh, Hh / 2, Hh);
        add_ln3_kernel<<<NTOK, 256>>>(px, py, py2,
                                      g1 + (size_t)l * Hh, be1 + (size_t)l * Hh);
        // FFN up + GELU
        gemm_mma<1><<<dim3(FFf / 128, 32, 1), 256, GSMEM>>>(
            pxhi, pwth + wl + OFF_W1, b1 + (size_t)l * FFf,
            nullptr, nullptr, nullptr, phhi, Hh, Hh, FFf);
        // FFN down: split-K=3
        gemm_mma<0><<<dim3(Hh / 128, 32, 3), 256, GSMEM>>>(
            phhi, pwth + wl + OFF_W2, b2 + (size_t)l * Hh,
            py, py2, py3, nullptr, FFf, FFf / 3, Hh);
        add_ln4_kernel<<<NTOK, 256>>>(px, py, py2, py3,
                                      g2 + (size_t)l * Hh, be2 + (size_t)l * Hh);
    }

    cls_kernel<<<Bb, 256>>>();
    reset_best_kernel<<<1, 32>>>();
    cos_kernel<<<(NLl + 127) / 128, 128>>>(lab, out);
    if (out_size >= Bb * NLl + Bb) ids_out_kernel<<<1, 32>>>(out);
}

// round 16
// speedup vs baseline: 1.0537x; 1.0220x over previous
#include <cuda_runtime.h>
#include <cuda_fp16.h>
#include <math.h>
#include <cstdint>

// ---------------- problem constants ----------------
#define Vv   30522
#define Hh   768
#define Ll   12
#define FFf  3072
#define NHh  12
#define DHh  64
#define Bb   32
#define Ss   128
#define NLl  10000
#define NTOK (Bb*Ss)          // 4096
#define QKVN (3*Hh)           // 2304
#define EPS_LN  1e-12f
#define EPS_COS 1e-8f

// transposed fp16 weight layout per layer (element offsets)
#define OFF_O   (QKVN*Hh)             // after packed qkv [2304][768]
#define OFF_W1  (OFF_O + Hh*Hh)       // [3072][768]
#define OFF_W2  (OFF_W1 + Hh*FFf)     // [768][3072]
#define LSTRIDE (OFF_W2 + FFf*Hh)     // 7,077,888

// ---------------- device scratch ----------------
__device__ __half g_wth[Ll*LSTRIDE];           // fp16 weights, transposed [N][K]
__device__ float  g_bqkv[Ll*QKVN];
__device__ float  g_zeros[Hh];                 // stays zero (module-load zero-init)

__device__ float  g_x  [NTOK*Hh];
__device__ __half g_xhi[NTOK*Hh];
__device__ float  g_qkv[NTOK*QKVN];
__device__ __half g_chi[NTOK*Hh];
__device__ __half g_hhi[NTOK*FFf];
__device__ float  g_y  [NTOK*Hh];
__device__ float  g_y2 [NTOK*Hh];
__device__ float  g_y3 [NTOK*Hh];
__device__ float g_mbias[NTOK];
__device__ float g_cls[Bb*Hh];
__device__ float g_cn [Bb];
__device__ unsigned long long g_best[Bb];

// ---------------- PTX helpers (compute_100-safe) ----------------
__device__ __forceinline__ uint32_t smem_u32(const void* p) {
    uint32_t a;
    asm("{ .reg .u64 t; cvta.to.shared.u64 t, %1; cvt.u32.u64 %0, t; }" : "=r"(a) : "l"(p));
    return a;
}
__device__ __forceinline__ void cp_async16(uint32_t dst, const void* src) {
    asm volatile("cp.async.cg.shared.global [%0], [%1], 16;" :: "r"(dst), "l"(src) : "memory");
}
#define CP_COMMIT() asm volatile("cp.async.commit_group;" ::: "memory")
#define CP_WAIT(n)  asm volatile("cp.async.wait_group %0;" :: "n"(n) : "memory")

__device__ __forceinline__ void ldsm4(uint32_t& r0, uint32_t& r1, uint32_t& r2, uint32_t& r3,
                                      uint32_t addr) {
    asm volatile("ldmatrix.sync.aligned.m8n8.x4.shared.b16 {%0,%1,%2,%3}, [%4];"
                 : "=r"(r0), "=r"(r1), "=r"(r2), "=r"(r3) : "r"(addr));
}
__device__ __forceinline__ void mma16816(float* c, uint32_t a0, uint32_t a1, uint32_t a2,
                                         uint32_t a3, uint32_t b0, uint32_t b1) {
    asm volatile(
        "mma.sync.aligned.m16n8k16.row.col.f32.f16.f16.f32 "
        "{%0,%1,%2,%3}, {%4,%5,%6,%7}, {%8,%9}, {%0,%1,%2,%3};"
        : "+f"(c[0]), "+f"(c[1]), "+f"(c[2]), "+f"(c[3])
        : "r"(a0), "r"(a1), "r"(a2), "r"(a3), "r"(b0), "r"(b1));
}

// ---------------- misc helpers ----------------
__device__ __forceinline__ float blk_sum256(float v, volatile float* sred) {
    int lane = threadIdx.x & 31, w = threadIdx.x >> 5;
    #pragma unroll
    for (int o = 16; o > 0; o >>= 1) v += __shfl_down_sync(0xffffffffu, v, o);
    if (lane == 0) sred[w] = v;
    __syncthreads();
    if (threadIdx.x == 0) {
        float s = 0.f;
        #pragma unroll
        for (int i = 0; i < 8; i++) s += sred[i];
        sred[8] = s;
    }
    __syncthreads();
    float r = sred[8];
    __syncthreads();
    return r;
}
__device__ __forceinline__ float gelu_tanh(float x) {
    float x3 = x * x * x;
    float t = tanhf(0.7978845608028654f * (x + 0.044715f * x3));
    return 0.5f * x * (1.0f + t);
}
__device__ __forceinline__ unsigned long long pack_key(float c, int l) {
    unsigned u = __float_as_uint(c);
    u = (u & 0x80000000u) ? ~u : (u | 0x80000000u);
    return ((unsigned long long)u << 32) | (unsigned long long)(0xFFFFFFFFu - (unsigned)l);
}
__device__ __forceinline__ unsigned pack2h(float v0, float v1) {
    __half h0 = __float2half(v0), h1 = __float2half(v1);
    return (unsigned)__half_as_ushort(h0) | ((unsigned)__half_as_ushort(h1) << 16);
}

// ---------------- weight transpose to fp16 ----------------
__global__ void wsplit4_kernel(const float* __restrict__ W0, const float* __restrict__ W1m,
                               const float* __restrict__ W2m, const float* __restrict__ W3m) {
    __shared__ float t[32][33];
    int z = blockIdx.z;
    int m = z & 3, l = z >> 2;
    const float* Ws = (m == 0 ? W0 : m == 1 ? W1m : m == 2 ? W2m : W3m) + (size_t)l * Hh * Hh;
    long dstOff = (m < 3) ? (long)m * Hh * Hh : (long)OFF_O;
    __half* th = g_wth + (size_t)l * LSTRIDE + dstOff;
    int n = blockIdx.x * 32 + threadIdx.x;
    #pragma unroll
    for (int i = 0; i < 4; i++) {
        int k = blockIdx.y * 32 + threadIdx.y + i * 8;
        t[threadIdx.y + i * 8][threadIdx.x] = Ws[(size_t)k * Hh + n];
    }
    __syncthreads();
    int k2 = blockIdx.y * 32 + threadIdx.x;
    #pragma unroll
    for (int i = 0; i < 4; i++) {
        int n2 = blockIdx.x * 32 + threadIdx.y + i * 8;
        th[(size_t)n2 * Hh + k2] = __float2half(t[threadIdx.x][threadIdx.y + i * 8]);
    }
}

__global__ void wsplit_kernel(const float* __restrict__ W, long dstOff, int K, int N) {
    __shared__ float t[32][33];
    int l = blockIdx.z;
    const float* Ws = W + (size_t)l * K * N;
    __half* th = g_wth + (size_t)l * LSTRIDE + dstOff;
    int n = blockIdx.x * 32 + threadIdx.x;
    #pragma unroll
    for (int i = 0; i < 4; i++) {
        int k = blockIdx.y * 32 + threadIdx.y + i * 8;
        t[threadIdx.y + i * 8][threadIdx.x] = Ws[(size_t)k * N + n];
    }
    __syncthreads();
    int k2 = blockIdx.y * 32 + threadIdx.x;
    #pragma unroll
    for (int i = 0; i < 4; i++) {
        int n2 = blockIdx.x * 32 + threadIdx.y + i * 8;
        th[(size_t)n2 * K + k2] = __float2half(t[threadIdx.x][threadIdx.y + i * 8]);
    }
}

__global__ void pack_bias_kernel(const float* __restrict__ bq, const float* __restrict__ bk,
                                 const float* __restrict__ bv) {
    int l = blockIdx.x, j = threadIdx.x;
    g_bqkv[l * QKVN + j]          = bq[l * Hh + j];
    g_bqkv[l * QKVN + Hh + j]     = bk[l * Hh + j];
    g_bqkv[l * QKVN + 2 * Hh + j] = bv[l * Hh + j];
}

// ---------------- embeddings + LN + mask bias ----------------
__global__ void embed_ln_kernel(const int* __restrict__ ids, const int* __restrict__ tys,
                                const float* __restrict__ word, const float* __restrict__ pos,
                                const float* __restrict__ typ,
                                const float* __restrict__ eg, const float* __restrict__ eb) {
    __shared__ float sred[9];
    int t = blockIdx.x;
    int s = t & (Ss - 1);
    int id = ids[t], ty = tys[t];
    float v[3];
    float loc = 0.f;
    #pragma unroll
    for (int i = 0; i < 3; i++) {
        int j = threadIdx.x + i * 256;
        v[i] = word[(size_t)id * Hh + j] + pos[(size_t)s * Hh + j] + typ[(size_t)ty * Hh + j];
        loc += v[i];
    }
    float mu = blk_sum256(loc, sred) * (1.0f / Hh);
    float l2 = 0.f;
    #pragma unroll
    for (int i = 0; i < 3; i++) { float d = v[i] - mu; l2 += d * d; }
    float var = blk_sum256(l2, sred) * (1.0f / Hh);
    float rstd = rsqrtf(var + EPS_LN);
    #pragma unroll
    for (int i = 0; i < 3; i++) {
        int j = threadIdx.x + i * 256;
        size_t idx = (size_t)t * Hh + j;
        float o = (v[i] - mu) * rstd * eg[j] + eb[j];
        g_x[idx] = o;
        g_xhi[idx] = __float2half(o);
    }
    if (threadIdx.x == 0) g_mbias[t] = (id > 0) ? 0.f : -10000.0f;
}

// ---------------- residual add (3-way) + LN ----------------
__global__ void add_ln3_kernel(float* __restrict__ x, const float* __restrict__ y,
                               const float* __restrict__ y2,
                               const float* __restrict__ g, const float* __restrict__ b) {
    __shared__ float sred[9];
    size_t base = (size_t)blockIdx.x * Hh;
    float v[3];
    float loc = 0.f;
    #pragma unroll
    for (int i = 0; i < 3; i++) {
        int j = threadIdx.x + i * 256;
        v[i] = x[base + j] + y[base + j] + y2[base + j];
        loc += v[i];
    }
    float mu = blk_sum256(loc, sred) * (1.0f / Hh);
    float l2 = 0.f;
    #pragma unroll
    for (int i = 0; i < 3; i++) { float d = v[i] - mu; l2 += d * d; }
    float var = blk_sum256(l2, sred) * (1.0f / Hh);
    float rstd = rsqrtf(var + EPS_LN);
    #pragma unroll
    for (int i = 0; i < 3; i++) {
        int j = threadIdx.x + i * 256;
        float o = (v[i] - mu) * rstd * g[j] + b[j];
        x[base + j] = o;
        g_xhi[base + j] = __float2half(o);
    }
}

// ---------------- residual add (4-way) + LN (for split-K3 W2) ----------------
__global__ void add_ln4_kernel(float* __restrict__ x, const float* __restrict__ y,
                               const float* __restrict__ y2, const float* __restrict__ y3,
                               const float* __restrict__ g, const float* __restrict__ b) {
    __shared__ float sred[9];
    size_t base = (size_t)blockIdx.x * Hh;
    float v[3];
    float loc = 0.f;
    #pragma unroll
    for (int i = 0; i < 3; i++) {
        int j = threadIdx.x + i * 256;
        v[i] = x[base + j] + y[base + j] + y2[base + j] + y3[base + j];
        loc += v[i];
    }
    float mu = blk_sum256(loc, sred) * (1.0f / Hh);
    float l2 = 0.f;
    #pragma unroll
    for (int i = 0; i < 3; i++) { float d = v[i] - mu; l2 += d * d; }
    float var = blk_sum256(l2, sred) * (1.0f / Hh);
    float rstd = rsqrtf(var + EPS_LN);
    #pragma unroll
    for (int i = 0; i < 3; i++) {
        int j = threadIdx.x + i * 256;
        float o = (v[i] - mu) * rstd * g[j] + b[j];
        x[base + j] = o;
        g_xhi[base + j] = __float2half(o);
    }
}

// ---------------- HMMA fp16 GEMM: C[4096, N] = Ah @ Bh^T + bias ----------------
// K-split via gridDim.z (OUTMODE 0): z=0 -> Cf with bias, z>=1 -> Cfz zero-bias.
// OUTMODE 1: gelu -> fp16 out. CTA 128x128, 4 warps (warp tile 64x64), K-chunk 64
// (rows 144B), 2-stage cp.async, 2 CTAs/SM. 8 ldsm : 32 mma per k16 per warp.
#define GT_ROW   144
#define GT_TILE  (128 * GT_ROW)        // 18432 B per sub-tile
#define GT_STAGE (2 * GT_TILE)         // Ah | Bh = 36864
#define GSMEM    (2 * GT_STAGE)        // 73728
template <int OUTMODE>
__global__ void __launch_bounds__(128, 2) gemm_mma(
    const __half* __restrict__ Ahi,
    const __half* __restrict__ Bh,
    const float* __restrict__ bias,
    float* __restrict__ Cf, float* __restrict__ Cf2, float* __restrict__ Cf3,
    __half* __restrict__ Chi,
    int Kfull, int Klen, int ldc)
{
    extern __shared__ char sm[];
    const uint32_t sb = smem_u32(sm);
    int tid = threadIdx.x, lane = tid & 31, wid = tid >> 5;
    int wm = wid >> 1, wn = wid & 1;              // warp tile rows wm*64, cols wn*64
    int m0 = blockIdx.y * 128, n0 = blockIdx.x * 128;
    int kz = blockIdx.z;
    int kbase = kz * Klen;
    const float* bsel = (OUTMODE == 0 && kz) ? g_zeros : bias;
    float* csel = Cf;
    if (OUTMODE == 0) {
        if (kz == 1) csel = Cf2;
        else if (kz == 2) csel = Cf3;
    }

    // ldmatrix lane offsets (row stride 144B)
    int q = lane >> 3, r = lane & 7;
    uint32_t aLane = (uint32_t)(((q & 1) * 8 + r) * GT_ROW + (q >> 1) * 16);
    uint32_t bLane = (uint32_t)(((q >> 1) * 8 + r) * GT_ROW + (q & 1) * 16);

    float acc[4][8][4];
    #pragma unroll
    for (int mi = 0; mi < 4; mi++)
        #pragma unroll
        for (int ni = 0; ni < 8; ni++)
            #pragma unroll
            for (int e = 0; e < 4; e++) acc[mi][ni][e] = 0.f;

    int nchunk = Klen >> 6;                       // K-chunk = 64

    // loader: 2 tiles x 128 rows x 8 segs of 16B = 2048 cp.async; 16 per thread
    auto load_stage = [&](int c) {
        int k0 = kbase + (c << 6);
        uint32_t base = sb + (uint32_t)(c & 1) * GT_STAGE;
        #pragma unroll
        for (int i = 0; i < 16; i++) {
            int lin = tid + i * 128;              // 0..2047
            int tsel = lin >> 10;                 // 0=Ah 1=Bh
            int within = lin & 1023;
            int row = within >> 3, seg = within & 7;
            const __half* src = (tsel == 0)
                ? Ahi + (size_t)(m0 + row) * Kfull + k0 + seg * 8
                : Bh  + (size_t)(n0 + row) * Kfull + k0 + seg * 8;
            cp_async16(base + (uint32_t)tsel * GT_TILE + (uint32_t)(row * GT_ROW + seg * 16),
                       src);
        }
    };

    load_stage(0);
    CP_COMMIT();

    for (int c = 0; c < nchunk; c++) {
        if (c + 1 < nchunk) { load_stage(c + 1); CP_COMMIT(); CP_WAIT(1); }
        else { CP_WAIT(0); }
        __syncthreads();

        uint32_t base = sb + (uint32_t)(c & 1) * GT_STAGE;
        uint32_t aBase = base + (uint32_t)((wm * 64) * GT_ROW) + aLane;
        uint32_t bBase = base + GT_TILE + (uint32_t)((wn * 64) * GT_ROW) + bLane;

        #pragma unroll
        for (int ks = 0; ks < 4; ks++) {
            uint32_t ko = (uint32_t)(ks * 32);
            uint32_t ah[4][4], bf[4][4];
            #pragma unroll
            for (int p = 0; p < 4; p++)
                ldsm4(bf[p][0], bf[p][1], bf[p][2], bf[p][3],
                      bBase + (uint32_t)(p * 16 * GT_ROW) + ko);
            #pragma unroll
            for (int mi = 0; mi < 4; mi++)
                ldsm4(ah[mi][0], ah[mi][1], ah[mi][2], ah[mi][3],
                      aBase + (uint32_t)(mi * 16 * GT_ROW) + ko);
            #pragma unroll
            for (int mi = 0; mi < 4; mi++)
                #pragma unroll
                for (int ni = 0; ni < 8; ni++) {
                    int p = ni >> 1, su = ni & 1;
                    mma16816(acc[mi][ni], ah[mi][0], ah[mi][1], ah[mi][2], ah[mi][3],
                             bf[p][su * 2], bf[p][su * 2 + 1]);
                }
        }
        __syncthreads();
    }

    // ---------------- epilogue ----------------
    int rbase = m0 + wm * 64 + (lane >> 2);
    int cbase = n0 + wn * 64 + (lane & 3) * 2;
    #pragma unroll
    for (int mi = 0; mi < 4; mi++) {
        #pragma unroll
        for (int ni = 0; ni < 8; ni++) {
            int row = rbase + mi * 16;
            int col = cbase + ni * 8;
            float b0 = bsel[col], b1 = bsel[col + 1];
            float v0 = acc[mi][ni][0] + b0, v1 = acc[mi][ni][1] + b1;
            float v2 = acc[mi][ni][2] + b0, v3 = acc[mi][ni][3] + b1;
            if (OUTMODE == 0) {
                *(float2*)(csel + (size_t)row * ldc + col)       = make_float2(v0, v1);
                *(float2*)(csel + (size_t)(row + 8) * ldc + col) = make_float2(v2, v3);
            } else {
                *(unsigned*)(Chi + (size_t)row * ldc + col) =
                    pack2h(gelu_tanh(v0), gelu_tanh(v1));
                *(unsigned*)(Chi + (size_t)(row + 8) * ldc + col) =
                    pack2h(gelu_tanh(v2), gelu_tanh(v3));
            }
        }
    }
}

// ---------------- attention: 256 threads, split j-range (QK) and d-range (PV) ----------------
#define ATTN_SMEM ((2*Ss*DHh + Ss*129 + Ss + 2*256) * (int)sizeof(float))
__global__ void __launch_bounds__(256) attn_kernel(const float* __restrict__ Qkv,
                                                   const float* __restrict__ bias,
                                                   __half* __restrict__ chi) {
    extern __shared__ float smf[];
    float* Ks = smf;                        // [128][64]
    float* Vs = smf + Ss * DHh;             // [128][64]
    float* S  = smf + 2 * Ss * DHh;         // [128][129]
    float* biasS = S + Ss * 129;            // [128]
    float* pm = biasS + Ss;                 // [256]
    float* ps = pm + 256;                   // [256]
    int bn = blockIdx.x;
    int b = bn / NHh, n = bn % NHh;
    int tid = threadIdx.x;
    int qi = tid & 127, h = tid >> 7;
    const float scale = 0.125f;

    #pragma unroll
    for (int i = 0; i < 8; i++) {
        int lin = tid + i * 256;
        int j = lin >> 4, c4 = (lin & 15) * 4;
        size_t rowb = (size_t)(b * Ss + j) * QKVN + n * DHh + c4;
        *(float4*)&Ks[j * DHh + c4] = *(const float4*)(Qkv + rowb + Hh);
        *(float4*)&Vs[j * DHh + c4] = *(const float4*)(Qkv + rowb + 2 * Hh);
    }
    if (tid < Ss) biasS[tid] = bias[b * Ss + tid];
    __syncthreads();

    float Qr[DHh];
    const float4* qp = (const float4*)(Qkv + (size_t)(b * Ss + qi) * QKVN + n * DHh);
    #pragma unroll
    for (int i = 0; i < 16; i++) {
        float4 v4 = qp[i];
        Qr[i * 4 + 0] = v4.x; Qr[i * 4 + 1] = v4.y; Qr[i * 4 + 2] = v4.z; Qr[i * 4 + 3] = v4.w;
    }

    float* Srow = S + qi * 129;
    int jbase = h * 64;
    float m = -1e30f;
    #pragma unroll 1
    for (int jj = 0; jj < 64; jj += 4) {
        int j = jbase + jj;
        const float4* k0 = (const float4*)(Ks + j * DHh);
        float s0 = 0.f, s1 = 0.f, s2 = 0.f, s3 = 0.f;
        #pragma unroll
        for (int i = 0; i < 16; i++) {
            float4 kv0 = k0[i];
            float4 kv1 = k0[16 + i];
            float4 kv2 = k0[32 + i];
            float4 kv3 = k0[48 + i];
            float q0 = Qr[i * 4], q1 = Qr[i * 4 + 1], q2 = Qr[i * 4 + 2], q3 = Qr[i * 4 + 3];
            s0 = fmaf(q0, kv0.x, s0); s0 = fmaf(q1, kv0.y, s0);
            s0 = fmaf(q2, kv0.z, s0); s0 = fmaf(q3, kv0.w, s0);
            s1 = fmaf(q0, kv1.x, s1); s1 = fmaf(q1, kv1.y, s1);
            s1 = fmaf(q2, kv1.z, s1); s1 = fmaf(q3, kv1.w, s1);
            s2 = fmaf(q0, kv2.x, s2); s2 = fmaf(q1, kv2.y, s2);
            s2 = fmaf(q2, kv2.z, s2); s2 = fmaf(q3, kv2.w, s2);
            s3 = fmaf(q0, kv3.x, s3); s3 = fmaf(q1, kv3.y, s3);
            s3 = fmaf(q2, kv3.z, s3); s3 = fmaf(q3, kv3.w, s3);
        }
        s0 = fmaf(s0, scale, biasS[j]);
        s1 = fmaf(s1, scale, biasS[j + 1]);
        s2 = fmaf(s2, scale, biasS[j + 2]);
        s3 = fmaf(s3, scale, biasS[j + 3]);
        Srow[j] = s0; Srow[j + 1] = s1; Srow[j + 2] = s2; Srow[j + 3] = s3;
        m = fmaxf(m, fmaxf(fmaxf(s0, s1), fmaxf(s2, s3)));
    }
    pm[h * 128 + qi] = m;
    __syncthreads();
    m = fmaxf(pm[qi], pm[128 + qi]);

    float ls = 0.f;
    #pragma unroll 4
    for (int jj = 0; jj < 64; jj++) {
        int j = jbase + jj;
        float p = __expf(Srow[j] - m);
        Srow[j] = p;
        ls += p;
    }
    ps[h * 128 + qi] = ls;
    __syncthreads();
    float inv_l = 1.0f / (ps[qi] + ps[128 + qi]);

    int dbase = h * 32;
    float acc[32];
    #pragma unroll
    for (int d = 0; d < 32; d++) acc[d] = 0.f;
    #pragma unroll 1
    for (int j = 0; j < Ss; j++) {
        float p = Srow[j];
        const float4* vr = (const float4*)(Vs + j * DHh + dbase);
        #pragma unroll
        for (int i = 0; i < 8; i++) {
            float4 v4 = vr[i];
            acc[i * 4 + 0] = fmaf(p, v4.x, acc[i * 4 + 0]);
            acc[i * 4 + 1] = fmaf(p, v4.y, acc[i * 4 + 1]);
            acc[i * 4 + 2] = fmaf(p, v4.z, acc[i * 4 + 2]);
            acc[i * 4 + 3] = fmaf(p, v4.w, acc[i * 4 + 3]);
        }
    }
    size_t obase = (size_t)(b * Ss + qi) * Hh + n * DHh + dbase;
    #pragma unroll
    for (int d = 0; d < 32; d += 2) {
        *(unsigned*)(chi + obase + d) = pack2h(acc[d] * inv_l, acc[d + 1] * inv_l);
    }
}

// ---------------- CLS extraction + norm ----------------
__global__ void cls_kernel() {
    __shared__ float sred[9];
    int b = blockIdx.x;
    float loc = 0.f;
    #pragma unroll
    for (int i = 0; i < 3; i++) {
        int j = threadIdx.x + i * 256;
        float v = g_x[(size_t)(b * Ss) * Hh + j];
        g_cls[b * Hh + j] = v;
        loc += v * v;
    }
    float s = blk_sum256(loc, sred);
    if (threadIdx.x == 0) g_cn[b] = fmaxf(sqrtf(s), EPS_COS);
}

__global__ void reset_best_kernel() {
    if (threadIdx.x < Bb) g_best[threadIdx.x] = 0ull;
}

// ---------------- cosine + per-block argmax reduction ----------------
__global__ void __launch_bounds__(128) cos_kernel(const float* __restrict__ lab,
                                                  float* __restrict__ out) {
    __shared__ float clsS[Bb][33];
    __shared__ float sInvCn[Bb];
    int l = blockIdx.x * 128 + threadIdx.x;
    bool valid = (l < NLl);
    if (threadIdx.x < Bb) sInvCn[threadIdx.x] = 1.0f / g_cn[threadIdx.x];

    float acc[Bb];
    #pragma unroll
    for (int bb = 0; bb < Bb; bb++) acc[bb] = 0.f;

    for (int k0 = 0; k0 < Hh; k0 += 32) {
        #pragma unroll
        for (int i = 0; i < 8; i++) {
            int idx = threadIdx.x + i * 128;
            int bb = idx >> 5, kk = idx & 31;
            clsS[bb][kk] = g_cls[bb * Hh + k0 + kk];
        }
        __syncthreads();
        if (valid) {
            float lv[32];
            const float4* lp = (const float4*)(lab + (size_t)l * Hh + k0);
            #pragma unroll
            for (int i = 0; i < 8; i++) {
                float4 v4 = lp[i];
                lv[i * 4] = v4.x; lv[i * 4 + 1] = v4.y; lv[i * 4 + 2] = v4.z; lv[i * 4 + 3] = v4.w;
            }
            #pragma unroll
            for (int bb = 0; bb < Bb; bb++) {
                float a = acc[bb];
                #pragma unroll
                for (int kk = 0; kk < 32; kk++) a = fmaf(clsS[bb][kk], lv[kk], a);
                acc[bb] = a;
            }
        }
        __syncthreads();
    }

    float invl = 0.f;
    if (valid) {
        float s = 0.f;
        const float4* lp = (const float4*)(lab + (size_t)l * Hh);
        #pragma unroll 4
        for (int i = 0; i < Hh / 4; i++) {
            float4 v4 = lp[i];
            s += v4.x * v4.x + v4.y * v4.y + v4.z * v4.z + v4.w * v4.w;
        }
        invl = 1.0f / fmaxf(sqrtf(s), EPS_COS);
    }

    int lane = threadIdx.x & 31;
    #pragma unroll 1
    for (int bb = 0; bb < Bb; bb++) {
        unsigned long long key = 0ull;
        if (valid) {
            float c = acc[bb] * invl * sInvCn[bb];
            out[(size_t)bb * NLl + l] = c;
            key = pack_key(c, l);
        }
        #pragma unroll
        for (int o = 16; o > 0; o >>= 1) {
            unsigned long long other = __shfl_down_sync(0xffffffffu, key, o);
            key = (other > key) ? other : key;
        }
        if (lane == 0) atomicMax(&g_best[bb], key);
    }
}

__global__ void ids_out_kernel(float* __restrict__ out) {
    int b = threadIdx.x;
    if (b < Bb) {
        unsigned idpart = (unsigned)(g_best[b] & 0xFFFFFFFFull);
        out[(size_t)Bb * NLl + b] = (float)(0xFFFFFFFFu - idpart);
    }
}

// ---------------- host orchestration ----------------
extern "C" void kernel_launch(void* const* d_in, const int* in_sizes, int n_in,
                              void* d_out, int out_size) {
    const int*   ids  = (const int*)d_in[0];
    const int*   tys  = (const int*)d_in[1];
    const float* word = (const float*)d_in[2];
    const float* pos  = (const float*)d_in[3];
    const float* typ  = (const float*)d_in[4];
    const float* eg   = (const float*)d_in[5];
    const float* eb   = (const float*)d_in[6];
    const float* Wq   = (const float*)d_in[7];
    const float* bq   = (const float*)d_in[8];
    const float* Wk   = (const float*)d_in[9];
    const float* bk   = (const float*)d_in[10];
    const float* Wv   = (const float*)d_in[11];
    const float* bv   = (const float*)d_in[12];
    const float* Wo   = (const float*)d_in[13];
    const float* bo   = (const float*)d_in[14];
    const float* g1   = (const float*)d_in[15];
    const float* be1  = (const float*)d_in[16];
    const float* W1   = (const float*)d_in[17];
    const float* b1   = (const float*)d_in[18];
    const float* W2   = (const float*)d_in[19];
    const float* b2   = (const float*)d_in[20];
    const float* g2   = (const float*)d_in[21];
    const float* be2  = (const float*)d_in[22];
    const float* lab  = (const float*)d_in[23];
    float* out = (float*)d_out;

    float *px, *py, *py2, *py3, *pqkv, *pmbias, *pbqkv;
    __half *pxhi, *pchi, *phhi, *pwth;
    cudaGetSymbolAddress((void**)&px,    g_x);
    cudaGetSymbolAddress((void**)&py,    g_y);
    cudaGetSymbolAddress((void**)&py2,   g_y2);
    cudaGetSymbolAddress((void**)&py3,   g_y3);
    cudaGetSymbolAddress((void**)&pqkv,  g_qkv);
    cudaGetSymbolAddress((void**)&pmbias,g_mbias);
    cudaGetSymbolAddress((void**)&pbqkv, g_bqkv);
    cudaGetSymbolAddress((void**)&pxhi,  g_xhi);
    cudaGetSymbolAddress((void**)&pchi,  g_chi);
    cudaGetSymbolAddress((void**)&phhi,  g_hhi);
    cudaGetSymbolAddress((void**)&pwth,  g_wth);

    cudaFuncSetAttribute(attn_kernel, cudaFuncAttributeMaxDynamicSharedMemorySize, ATTN_SMEM);
    cudaFuncSetAttribute(gemm_mma<0>, cudaFuncAttributeMaxDynamicSharedMemorySize, GSMEM);
    cudaFuncSetAttribute(gemm_mma<1>, cudaFuncAttributeMaxDynamicSharedMemorySize, GSMEM);

    dim3 tb(32, 8);
    wsplit4_kernel<<<dim3(24, 24, 48), tb>>>(Wq, Wk, Wv, Wo);                 // 1
    embed_ln_kernel<<<NTOK, 256>>>(ids, tys, word, pos, typ, eg, eb);         // 2
    pack_bias_kernel<<<Ll, Hh>>>(bq, bk, bv);                                 // 3

    for (int l = 0; l < Ll; l++) {
        size_t wl = (size_t)l * LSTRIDE;
        // QKV
        gemm_mma<0><<<dim3(QKVN / 128, 32, 1), 128, GSMEM>>>(                 // 4 on l==0
            pxhi, pwth + wl, pbqkv + l * QKVN,
            pqkv, nullptr, nullptr, nullptr, Hh, Hh, QKVN);
        attn_kernel<<<Bb * NHh, 256, ATTN_SMEM>>>(pqkv, pmbias, pchi);
        if (l == 0) {
            wsplit_kernel<<<dim3(FFf / 32, Hh / 32, Ll), tb>>>(W1, OFF_W1, Hh, FFf);
            wsplit_kernel<<<dim3(Hh / 32, FFf / 32, Ll), tb>>>(W2, OFF_W2, FFf, Hh);
        }
        // O projection: split-K=2
        gemm_mma<0><<<dim3(Hh / 128, 32, 2), 128, GSMEM>>>(
            pchi, pwth + wl + OFF_O, bo + (size_t)l * Hh,
            py, py2, nullptr, nullptr, Hh, Hh / 2, Hh);
        add_ln3_kernel<<<NTOK, 256>>>(px, py, py2,
                                      g1 + (size_t)l * Hh, be1 + (size_t)l * Hh);
        // FFN up + GELU
        gemm_mma<1><<<dim3(FFf / 128, 32, 1), 128, GSMEM>>>(
            pxhi, pwth + wl + OFF_W1, b1 + (size_t)l * FFf,
            nullptr, nullptr, nullptr, phhi, Hh, Hh, FFf);
        // FFN down: split-K=3
        gemm_mma<0><<<dim3(Hh / 128, 32, 3), 128, GSMEM>>>(
            phhi, pwth + wl + OFF_W2, b2 + (size_t)l * Hh,
            py, py2, py3, nullptr, FFf, FFf / 3, Hh);
        add_ln4_kernel<<<NTOK, 256>>>(px, py, py2, py3,
                                      g2 + (size_t)l * Hh, be2 + (size_t)l * Hh);
    }

    cls_kernel<<<Bb, 256>>>();
    reset_best_kernel<<<1, 32>>>();
    cos_kernel<<<(NLl + 127) / 128, 128>>>(lab, out);
    if (out_size >= Bb * NLl + Bb) ids_out_kernel<<<1, 32>>>(out);
}